// round 15
// baseline (speedup 1.0000x reference)
#include <cuda_runtime.h>
#include <cuda_fp16.h>
#include <math.h>
#include <stdint.h>

#define NN 8192
#define KK 512
#define FF 64
#define SPLITJ 16
#define JCHUNK (NN / SPLITJ)   // 512
#define BI 64
#define BJ 64
#define NT (JCHUNK / BJ)       // 8

// k_attn smem layout (bytes)
#define HTSTG 9216
#define SM_HT 0                      // 6 stages = 55296
#define SM_P  (6 * HTSTG)            // 2 x 9216
#define SM_HR (SM_P + 2 * HTSTG)     // 2048
#define SM_BYTES (SM_HR + 2048)      // 75776

__device__ float g_hl[NN];
__device__ float g_hr[NN];
__device__ float g_scalars[4];                    // [1]=|W_ei| [2]=|W_si|
__device__ unsigned g_hrmaxkey;                   // order-preserving float key
__device__ uint32_t g_hT[128u * 2048u];           // [tile][f][jpair] f16x2, 1 MB
__device__ uint32_t g_mask[(size_t)NN * (NN / 32)]; // 8 MB adjacency bitmask
__device__ float g_acc[(size_t)SPLITJ * NN * FF]; // 32 MB
__device__ float g_Z[SPLITJ * NN];

// ---------- helpers ----------
__device__ __forceinline__ unsigned long long pk2(float x, float y) {
    unsigned long long r; asm("mov.b64 %0, {%1,%2};" : "=l"(r) : "f"(x), "f"(y)); return r;
}
__device__ __forceinline__ void fma2(unsigned long long& d, unsigned long long a, unsigned long long b) {
    asm("fma.rn.f32x2 %0, %1, %2, %0;" : "+l"(d) : "l"(a), "l"(b));
}
__device__ __forceinline__ float2 upk(unsigned long long v) {
    float2 f; asm("mov.b64 {%0,%1}, %2;" : "=f"(f.x), "=f"(f.y) : "l"(v)); return f;
}
__device__ __forceinline__ uint32_t smem_u32(const void* p) {
    uint32_t a; asm("{ .reg .u64 t; cvta.to.shared.u64 t, %1; cvt.u32.u64 %0, t; }" : "=r"(a) : "l"(p)); return a;
}
__device__ __forceinline__ void cpa16(uint32_t dst, const void* src) {
    asm volatile("cp.async.cg.shared.global [%0], [%1], 16;" :: "r"(dst), "l"(src));
}
#define CP_COMMIT()  asm volatile("cp.async.commit_group;" ::: "memory")
#define CP_WAIT1()   asm volatile("cp.async.wait_group 1;" ::: "memory")
#define CP_WAIT4()   asm volatile("cp.async.wait_group 4;" ::: "memory")
#define CP_WAITALL() asm volatile("cp.async.wait_all;" ::: "memory")

__device__ __forceinline__ uint32_t f16x2_of(float lo, float hi) {
    uint32_t r; asm("cvt.rn.f16x2.f32 %0, %1, %2;" : "=r"(r) : "f"(hi), "f"(lo)); return r;
}
__device__ __forceinline__ void ldm4(uint32_t* r, uint32_t addr) {
    asm volatile("ldmatrix.sync.aligned.m8n8.x4.shared.b16 {%0,%1,%2,%3}, [%4];"
                 : "=r"(r[0]), "=r"(r[1]), "=r"(r[2]), "=r"(r[3]) : "r"(addr));
}
__device__ __forceinline__ void mma16816(float* d, const uint32_t* a, uint32_t b0, uint32_t b1) {
    asm("mma.sync.aligned.m16n8k16.row.col.f32.f16.f16.f32 "
        "{%0,%1,%2,%3}, {%4,%5,%6,%7}, {%8,%9}, {%0,%1,%2,%3};"
        : "+f"(d[0]), "+f"(d[1]), "+f"(d[2]), "+f"(d[3])
        : "r"(a[0]), "r"(a[1]), "r"(a[2]), "r"(a[3]), "r"(b0), "r"(b1));
}
__device__ __forceinline__ unsigned fkey(float f) {
    unsigned u = __float_as_uint(f);
    return (u & 0x80000000u) ? ~u : (u | 0x80000000u);
}
__device__ __forceinline__ float fkeyinv(unsigned k) {
    unsigned u = (k & 0x80000000u) ? (k ^ 0x80000000u) : ~k;
    return __uint_as_float(u);
}

// ============ M: adjacency bitmask (ballot-compress, max-BW stream) ============
__global__ void __launch_bounds__(256) k_mask(const int* __restrict__ adj) {
    __shared__ uint32_t buf[8][32];
    const int t = threadIdx.x, wid = t >> 5, l = t & 31;
    const size_t wbase = ((size_t)blockIdx.x * 8 + wid) * 32;   // this warp's 32 words
#pragma unroll 4
    for (int s = 0; s < 32; s++) {
        int v = adj[(wbase + (size_t)s) * 32 + l];
        unsigned b = __ballot_sync(0xffffffffu, v > 0);
        if (l == s) buf[wid][s] = b;
    }
    __syncwarp();
    if (l < 8) *(uint4*)&g_mask[wbase + l * 4] = *(uint4*)&buf[wid][l * 4];
}

// ============ A: pipelined gemm + fused hl/hr/hrmax + fp16 hT image ============
__global__ void __launch_bounds__(128) k_gemm_h(const float* __restrict__ X,
                                                const float* __restrict__ W,
                                                const float* __restrict__ a,
                                                const float* __restrict__ Wsi,
                                                const float* __restrict__ Wei) {
    __shared__ float xs[32][36];
    __shared__ float ws[3][32][68];
    __shared__ float as1[FF], as2[FF], red[128];
    const int t = threadIdx.x, tx = t & 15, ty = t >> 4;
    const int i0 = blockIdx.x * 32;
    if (t < FF) as1[t] = a[t]; else as2[t - FF] = a[t];

    const uint32_t ws_sb = smem_u32(&ws[0][0][0]);
    auto issueW = [&](int s, int c0) {
#pragma unroll
        for (int k = 0; k < 4; k++) {
            int c = k * 128 + t, row = c >> 4, col4 = (c & 15) * 4;
            cpa16(ws_sb + (uint32_t)((s * 2176 + row * 68 + col4) * 4),
                  W + (size_t)(c0 + row) * FF + col4);
        }
    };
    const int xrow = t >> 2, xk0 = (t & 3) * 8;
    float4 xr0, xr1;
    auto loadX = [&](int c0) {
        const float* p = &X[(size_t)(i0 + xrow) * KK + c0 + xk0];
        xr0 = *(const float4*)p; xr1 = *(const float4*)(p + 4);
    };

    issueW(0, 0);  CP_COMMIT();
    issueW(1, 32); CP_COMMIT();
    loadX(0);

    unsigned long long acc[4][2];
#pragma unroll
    for (int r = 0; r < 4; r++) { acc[r][0] = 0ULL; acc[r][1] = 0ULL; }

    for (int ct = 0; ct < 16; ct++) {
        CP_WAIT1();
        __syncthreads();
        xs[xk0 + 0][xrow] = xr0.x; xs[xk0 + 1][xrow] = xr0.y;
        xs[xk0 + 2][xrow] = xr0.z; xs[xk0 + 3][xrow] = xr0.w;
        xs[xk0 + 4][xrow] = xr1.x; xs[xk0 + 5][xrow] = xr1.y;
        xs[xk0 + 6][xrow] = xr1.z; xs[xk0 + 7][xrow] = xr1.w;
        if (ct + 1 < 16) loadX(32 * (ct + 1));
        { int cs = (ct + 2 < 16) ? ct + 2 : 15; issueW((ct + 2) % 3, 32 * cs); }
        CP_COMMIT();
        __syncthreads();
        const int st = ct % 3;
#pragma unroll
        for (int kk = 0; kk < 32; kk++) {
            float4 w4 = *(const float4*)&ws[st][kk][4 * tx];
            unsigned long long w01 = pk2(w4.x, w4.y), w23 = pk2(w4.z, w4.w);
            float4 a4 = *(const float4*)&xs[kk][4 * ty];
            float av[4] = {a4.x, a4.y, a4.z, a4.w};
#pragma unroll
            for (int r = 0; r < 4; r++) {
                unsigned long long ar = pk2(av[r], av[r]);
                fma2(acc[r][0], ar, w01); fma2(acc[r][1], ar, w23);
            }
        }
    }
    CP_WAITALL();

    float av[4][4];
#pragma unroll
    for (int r = 0; r < 4; r++) {
        float2 lo = upk(acc[r][0]), hi = upk(acc[r][1]);
        av[r][0] = lo.x; av[r][1] = lo.y; av[r][2] = hi.x; av[r][3] = hi.y;
    }
    {
        const int T = blockIdx.x >> 1;
        const uint32_t jp = (uint32_t)((blockIdx.x & 1) * 16 + 2 * ty);
#pragma unroll
        for (int c = 0; c < 4; c++) {
            int f = 4 * tx + c;
            uint32_t bidx = (uint32_t)T * 2048u + (uint32_t)f * 32u + jp;
            g_hT[bidx]     = f16x2_of(av[0][c], av[1][c]);
            g_hT[bidx + 1] = f16x2_of(av[2][c], av[3][c]);
        }
    }
    float mloc = -3.4e38f;
#pragma unroll
    for (int r = 0; r < 4; r++) {
        float s1 = av[r][0]*as1[4*tx] + av[r][1]*as1[4*tx+1] + av[r][2]*as1[4*tx+2] + av[r][3]*as1[4*tx+3];
        float s2 = av[r][0]*as2[4*tx] + av[r][1]*as2[4*tx+1] + av[r][2]*as2[4*tx+2] + av[r][3]*as2[4*tx+3];
#pragma unroll
        for (int off = 8; off >= 1; off >>= 1) {
            s1 += __shfl_xor_sync(0xffffffffu, s1, off);
            s2 += __shfl_xor_sync(0xffffffffu, s2, off);
        }
        if (tx == 0) { g_hl[i0 + 4 * ty + r] = s1; g_hr[i0 + 4 * ty + r] = s2; }
        mloc = fmaxf(mloc, s2);
    }
    red[t] = mloc;
    __syncthreads();
    for (int s = 64; s > 0; s >>= 1) { if (t < s) red[t] = fmaxf(red[t], red[t + s]); __syncthreads(); }
    if (t == 0) atomicMax(&g_hrmaxkey, fkey(red[0]));
    if (blockIdx.x == 0 && t == 0) { g_scalars[1] = fabsf(Wei[0]); g_scalars[2] = fabsf(Wsi[0]); }
}

// ============ D: fused attention (bitmask, 2-deep ad prefetch, 6-stage Ht ring) ============
__global__ void __launch_bounds__(256, 2) k_attn(const float* __restrict__ adj_ad) {
    extern __shared__ float4 smem4[];
    char* base = (char*)smem4;
    const uint32_t sb = smem_u32(base);

    const int t = threadIdx.x, wid = t >> 5, l = t & 31;
    const int i0 = blockIdx.x * BI, split = blockIdx.y, j0b = split * JCHUNK;
    const int T0 = split * NT;

    if (t < 128) *(float4*)(base + SM_HR + 16 * t) = *(const float4*)&g_hr[j0b + 4 * t];

    const float hrmax = fkeyinv(g_hrmaxkey);
    const float wei = g_scalars[1], wsi = g_scalars[2];
    const int r1 = t >> 2, q1 = t & 3;
    const float hl_r = g_hl[i0 + r1];
    float smax = hl_r + hrmax;
    const float m_r = fmaf(wei, fmaxf(smax, 0.2f * smax), wsi);

    const int iw = wid & 3, fh = wid >> 2;
    const uint32_t aRow = (uint32_t)((l & 7) | (l & 8));
    const uint32_t aOff = (uint32_t)(16 * iw + aRow) * 144u + (uint32_t)(((l >> 4) & 1) * 16);
    const uint32_t bRow = (uint32_t)(32 * fh + ((l & 7) | (((l >> 4) & 1) << 3)));
    const uint32_t bOff = bRow * 144u + (uint32_t)(((l >> 3) & 1) * 16);

    float acc[16];
#pragma unroll
    for (int i = 0; i < 16; i++) acc[i] = 0.f;
    float zl = 0.f;

    // Ht ring prologue
#pragma unroll
    for (int s = 0; s < 5; s++) {
        const char* src = (const char*)&g_hT[(uint32_t)(T0 + s) * 2048u];
#pragma unroll
        for (int k = 0; k < 2; k++) {
            int c = k * 256 + t, f = c >> 3, ch = c & 7;
            cpa16(sb + SM_HT + s * HTSTG + f * 144 + ch * 16, src + f * 128 + ch * 16);
        }
        CP_COMMIT();
    }
    // ad tiles 0,1 in regs; mask word for tile 0
    const uint32_t* maskrow = &g_mask[(size_t)(i0 + r1) * (NN / 32) + split * 16];
    float4 adreg[2][4];
#pragma unroll
    for (int s = 0; s < 2; s++) {
        const float4* ap = (const float4*)&adj_ad[(size_t)(i0 + r1) * NN + j0b + s * BJ + q1 * 16];
#pragma unroll
        for (int k = 0; k < 4; k++) adreg[s][k] = ap[k];
    }
    uint32_t mw = maskrow[q1 >> 1];
    const int msh = (q1 & 1) * 16;
    __syncthreads();   // hr visible

    for (int jt = 0; jt < NT; jt++) {
        const int cur = jt & 1;
        // ---- phase 1 (registers): p -> fp16 into P[cur] ----
        {
            const float* hrs = (const float*)(base + SM_HR) + jt * 64 + q1 * 16;
            const uint32_t bits = mw >> msh;
            uint32_t pw[8];
#pragma unroll
            for (int k = 0; k < 4; k++) {
                float4 ad4 = adreg[cur][k];
                float4 hr4 = *(const float4*)(hrs + 4 * k);
                float pv[4];
                {
                    float s = hl_r + hr4.x, lr = fmaxf(s, 0.2f * s);
                    pv[0] = (bits & (1u << (4 * k + 0))) ? __expf(fmaf(wei, lr, fmaf(wsi, ad4.x, -m_r))) : 0.f;
                }
                {
                    float s = hl_r + hr4.y, lr = fmaxf(s, 0.2f * s);
                    pv[1] = (bits & (1u << (4 * k + 1))) ? __expf(fmaf(wei, lr, fmaf(wsi, ad4.y, -m_r))) : 0.f;
                }
                {
                    float s = hl_r + hr4.z, lr = fmaxf(s, 0.2f * s);
                    pv[2] = (bits & (1u << (4 * k + 2))) ? __expf(fmaf(wei, lr, fmaf(wsi, ad4.z, -m_r))) : 0.f;
                }
                {
                    float s = hl_r + hr4.w, lr = fmaxf(s, 0.2f * s);
                    pv[3] = (bits & (1u << (4 * k + 3))) ? __expf(fmaf(wei, lr, fmaf(wsi, ad4.w, -m_r))) : 0.f;
                }
                zl += (pv[0] + pv[1]) + (pv[2] + pv[3]);
                pw[2*k]   = f16x2_of(pv[0], pv[1]);
                pw[2*k+1] = f16x2_of(pv[2], pv[3]);
            }
            char* pb = base + SM_P + cur * HTSTG + r1 * 144 + q1 * 32;
            *(uint4*)pb        = make_uint4(pw[0], pw[1], pw[2], pw[3]);
            *(uint4*)(pb + 16) = make_uint4(pw[4], pw[5], pw[6], pw[7]);
        }

        // refill ad (2 ahead) and mask (1 ahead)
        if (jt + 2 < NT) {
            const float4* ap = (const float4*)&adj_ad[(size_t)(i0 + r1) * NN + j0b + (jt + 2) * BJ + q1 * 16];
#pragma unroll
            for (int k = 0; k < 4; k++) adreg[cur][k] = ap[k];
        }
        if (jt + 1 < NT) mw = maskrow[(jt + 1) * 2 + (q1 >> 1)];

        CP_WAIT4();
        __syncthreads();

        // issue Ht(jt+5)
        {
            const int jsrc = (jt + 5 < NT) ? jt + 5 : NT - 1;
            const char* src = (const char*)&g_hT[(uint32_t)(T0 + jsrc) * 2048u];
            const int st = (jt + 5) % 6;
#pragma unroll
            for (int k = 0; k < 2; k++) {
                int c = k * 256 + t, f = c >> 3, ch = c & 7;
                cpa16(sb + SM_HT + st * HTSTG + f * 144 + ch * 16, src + f * 128 + ch * 16);
            }
            CP_COMMIT();
        }

        // ---- phase 2: 16 mma ----
        const uint32_t pA = sb + SM_P + (uint32_t)(cur * HTSTG) + aOff;
        const uint32_t hB = sb + SM_HT + (uint32_t)((jt % 6) * HTSTG) + bOff;
#pragma unroll
        for (int ks = 0; ks < 4; ks++) {
            const uint32_t ka = (uint32_t)ks * 32u;
            uint32_t ap4[4], bh0[4], bh1[4];
            ldm4(ap4, pA + ka);
            ldm4(bh0, hB + ka);
            ldm4(bh1, hB + 16u * 144u + ka);
            mma16816(acc + 0,  ap4, bh0[0], bh0[1]);
            mma16816(acc + 4,  ap4, bh0[2], bh0[3]);
            mma16816(acc + 8,  ap4, bh1[0], bh1[1]);
            mma16816(acc + 12, ap4, bh1[2], bh1[3]);
        }
    }
    CP_WAITALL();

    zl += __shfl_xor_sync(0xffffffffu, zl, 1);
    zl += __shfl_xor_sync(0xffffffffu, zl, 2);
    if (q1 == 0) g_Z[split * NN + i0 + r1] = zl;

    {
        const int g = l >> 2, tig = l & 3;
#pragma unroll
        for (int nt = 0; nt < 4; nt++) {
            const int col = 32 * fh + 8 * nt + 2 * tig;
            const size_t b0 = ((size_t)split * NN + i0 + 16 * iw + g) * FF + col;
            const size_t b1 = b0 + (size_t)8 * FF;
            *(float2*)&g_acc[b0] = make_float2(acc[4 * nt + 0], acc[4 * nt + 1]);
            *(float2*)&g_acc[b1] = make_float2(acc[4 * nt + 2], acc[4 * nt + 3]);
        }
    }
}

// ============ E: combine (float4), normalize, ELU ============
__global__ void __launch_bounds__(256) k_combine(float* __restrict__ out) {
    const int v = blockIdx.x * 256 + threadIdx.x;
    const int i = v >> 4;
    float4 num = make_float4(0.f, 0.f, 0.f, 0.f);
    float den = 0.f;
#pragma unroll
    for (int s = 0; s < SPLITJ; s++) {
        float4 x = *(const float4*)&g_acc[(size_t)s * NN * FF + (size_t)v * 4];
        num.x += x.x; num.y += x.y; num.z += x.z; num.w += x.w;
        den += g_Z[s * NN + i];
    }
    float inv = 1.0f / den;
    float4 r = make_float4(num.x * inv, num.y * inv, num.z * inv, num.w * inv);
    r.x = (r.x > 0.f) ? r.x : expm1f(r.x);
    r.y = (r.y > 0.f) ? r.y : expm1f(r.y);
    r.z = (r.z > 0.f) ? r.z : expm1f(r.z);
    r.w = (r.w > 0.f) ? r.w : expm1f(r.w);
    *(float4*)&out[(size_t)v * 4] = r;
}

extern "C" void kernel_launch(void* const* d_in, const int* in_sizes, int n_in,
                              void* d_out, int out_size) {
    (void)in_sizes; (void)n_in; (void)out_size;
    const float* input  = (const float*)d_in[0];
    const float* W      = (const float*)d_in[1];
    const float* a      = (const float*)d_in[2];
    const float* W_si   = (const float*)d_in[3];
    const float* W_ei   = (const float*)d_in[4];
    const float* adj_ad = (const float*)d_in[5];
    const int*   adj    = (const int*)d_in[6];
    float* out = (float*)d_out;

    cudaFuncSetAttribute(k_attn, cudaFuncAttributeMaxDynamicSharedMemorySize, SM_BYTES);

    k_mask<<<NN * (NN / 32) / 256, 256>>>(adj);
    k_gemm_h<<<NN / 32, 128>>>(input, W, a, W_si, W_ei);
    k_attn<<<dim3(NN / BI, SPLITJ), 256, SM_BYTES>>>(adj_ad);
    k_combine<<<NN * FF / 1024, 256>>>(out);
}

// round 16
// speedup vs baseline: 1.1202x; 1.1202x over previous
#include <cuda_runtime.h>
#include <cuda_fp16.h>
#include <math.h>
#include <stdint.h>

#define NN 8192
#define KK 512
#define FF 64
#define SPLITJ 16
#define JCHUNK (NN / SPLITJ)   // 512
#define BI 64
#define BJ 64
#define NT (JCHUNK / BJ)       // 8

// k_attn smem layout (bytes)
#define HTSTG 9216
#define SM_HT 0                      // 6 stages = 55296
#define SM_P  (6 * HTSTG)            // 2 x 9216
#define SM_HR (SM_P + 2 * HTSTG)     // 2048
#define SM_BYTES (SM_HR + 2048)      // 75776

__device__ float g_hl[NN];
__device__ float g_hr[NN];
__device__ float g_scalars[4];                      // [1]=|W_ei| [2]=|W_si|
__device__ unsigned g_hrmaxkey;                     // order-preserving float key
__device__ uint32_t g_hT[128u * 2048u];             // [tile][f][jpair] f16x2, 1 MB
__device__ uint32_t g_mask[(size_t)NN * (NN / 32)]; // 8 MB adjacency bitmask
__device__ float g_acc[(size_t)SPLITJ * NN * FF];   // 32 MB
__device__ float g_Z[SPLITJ * NN];

// ---------- helpers ----------
__device__ __forceinline__ unsigned long long pk2(float x, float y) {
    unsigned long long r; asm("mov.b64 %0, {%1,%2};" : "=l"(r) : "f"(x), "f"(y)); return r;
}
__device__ __forceinline__ void fma2(unsigned long long& d, unsigned long long a, unsigned long long b) {
    asm("fma.rn.f32x2 %0, %1, %2, %0;" : "+l"(d) : "l"(a), "l"(b));
}
__device__ __forceinline__ float2 upk(unsigned long long v) {
    float2 f; asm("mov.b64 {%0,%1}, %2;" : "=f"(f.x), "=f"(f.y) : "l"(v)); return f;
}
__device__ __forceinline__ uint32_t smem_u32(const void* p) {
    uint32_t a; asm("{ .reg .u64 t; cvta.to.shared.u64 t, %1; cvt.u32.u64 %0, t; }" : "=r"(a) : "l"(p)); return a;
}
__device__ __forceinline__ void cpa16(uint32_t dst, const void* src) {
    asm volatile("cp.async.cg.shared.global [%0], [%1], 16;" :: "r"(dst), "l"(src));
}
#define CP_COMMIT()  asm volatile("cp.async.commit_group;" ::: "memory")
#define CP_WAIT1()   asm volatile("cp.async.wait_group 1;" ::: "memory")
#define CP_WAIT4()   asm volatile("cp.async.wait_group 4;" ::: "memory")
#define CP_WAITALL() asm volatile("cp.async.wait_all;" ::: "memory")

__device__ __forceinline__ uint32_t f16x2_of(float lo, float hi) {
    uint32_t r; asm("cvt.rn.f16x2.f32 %0, %1, %2;" : "=r"(r) : "f"(hi), "f"(lo)); return r;
}
__device__ __forceinline__ void ldm4(uint32_t* r, uint32_t addr) {
    asm volatile("ldmatrix.sync.aligned.m8n8.x4.shared.b16 {%0,%1,%2,%3}, [%4];"
                 : "=r"(r[0]), "=r"(r[1]), "=r"(r[2]), "=r"(r[3]) : "r"(addr));
}
__device__ __forceinline__ void mma16816(float* d, const uint32_t* a, uint32_t b0, uint32_t b1) {
    asm("mma.sync.aligned.m16n8k16.row.col.f32.f16.f16.f32 "
        "{%0,%1,%2,%3}, {%4,%5,%6,%7}, {%8,%9}, {%0,%1,%2,%3};"
        : "+f"(d[0]), "+f"(d[1]), "+f"(d[2]), "+f"(d[3])
        : "r"(a[0]), "r"(a[1]), "r"(a[2]), "r"(a[3]), "r"(b0), "r"(b1));
}
__device__ __forceinline__ unsigned fkey(float f) {
    unsigned u = __float_as_uint(f);
    return (u & 0x80000000u) ? ~u : (u | 0x80000000u);
}
__device__ __forceinline__ float fkeyinv(unsigned k) {
    unsigned u = (k & 0x80000000u) ? (k ^ 0x80000000u) : ~k;
    return __uint_as_float(u);
}

// ============ M: adjacency bitmask (ballot-compress, streaming) ============
__global__ void __launch_bounds__(256) k_mask(const int* __restrict__ adj) {
    __shared__ uint32_t buf[8][32];
    const int t = threadIdx.x, wid = t >> 5, l = t & 31;
    const size_t wbase = ((size_t)blockIdx.x * 8 + wid) * 32;
#pragma unroll 4
    for (int s = 0; s < 32; s++) {
        int v = adj[(wbase + (size_t)s) * 32 + l];
        unsigned b = __ballot_sync(0xffffffffu, v > 0);
        if (l == s) buf[wid][s] = b;
    }
    __syncwarp();
    if (l < 8) *(uint4*)&g_mask[wbase + l * 4] = *(uint4*)&buf[wid][l * 4];
}

// ============ A: pipelined gemm + fused hl/hr/hrmax + fp16 hT image ============
__global__ void __launch_bounds__(128) k_gemm_h(const float* __restrict__ X,
                                                const float* __restrict__ W,
                                                const float* __restrict__ a,
                                                const float* __restrict__ Wsi,
                                                const float* __restrict__ Wei) {
    __shared__ float xs[32][36];
    __shared__ float ws[3][32][68];
    __shared__ float as1[FF], as2[FF], red[128];
    const int t = threadIdx.x, tx = t & 15, ty = t >> 4;
    const int i0 = blockIdx.x * 32;
    if (t < FF) as1[t] = a[t]; else as2[t - FF] = a[t];

    const uint32_t ws_sb = smem_u32(&ws[0][0][0]);
    auto issueW = [&](int s, int c0) {
#pragma unroll
        for (int k = 0; k < 4; k++) {
            int c = k * 128 + t, row = c >> 4, col4 = (c & 15) * 4;
            cpa16(ws_sb + (uint32_t)((s * 2176 + row * 68 + col4) * 4),
                  W + (size_t)(c0 + row) * FF + col4);
        }
    };
    const int xrow = t >> 2, xk0 = (t & 3) * 8;
    float4 xr0, xr1;
    auto loadX = [&](int c0) {
        const float* p = &X[(size_t)(i0 + xrow) * KK + c0 + xk0];
        xr0 = *(const float4*)p; xr1 = *(const float4*)(p + 4);
    };

    issueW(0, 0);  CP_COMMIT();
    issueW(1, 32); CP_COMMIT();
    loadX(0);

    unsigned long long acc[4][2];
#pragma unroll
    for (int r = 0; r < 4; r++) { acc[r][0] = 0ULL; acc[r][1] = 0ULL; }

    for (int ct = 0; ct < 16; ct++) {
        CP_WAIT1();
        __syncthreads();
        xs[xk0 + 0][xrow] = xr0.x; xs[xk0 + 1][xrow] = xr0.y;
        xs[xk0 + 2][xrow] = xr0.z; xs[xk0 + 3][xrow] = xr0.w;
        xs[xk0 + 4][xrow] = xr1.x; xs[xk0 + 5][xrow] = xr1.y;
        xs[xk0 + 6][xrow] = xr1.z; xs[xk0 + 7][xrow] = xr1.w;
        if (ct + 1 < 16) loadX(32 * (ct + 1));
        { int cs = (ct + 2 < 16) ? ct + 2 : 15; issueW((ct + 2) % 3, 32 * cs); }
        CP_COMMIT();
        __syncthreads();
        const int st = ct % 3;
#pragma unroll
        for (int kk = 0; kk < 32; kk++) {
            float4 w4 = *(const float4*)&ws[st][kk][4 * tx];
            unsigned long long w01 = pk2(w4.x, w4.y), w23 = pk2(w4.z, w4.w);
            float4 a4 = *(const float4*)&xs[kk][4 * ty];
            float av[4] = {a4.x, a4.y, a4.z, a4.w};
#pragma unroll
            for (int r = 0; r < 4; r++) {
                unsigned long long ar = pk2(av[r], av[r]);
                fma2(acc[r][0], ar, w01); fma2(acc[r][1], ar, w23);
            }
        }
    }
    CP_WAITALL();

    float av[4][4];
#pragma unroll
    for (int r = 0; r < 4; r++) {
        float2 lo = upk(acc[r][0]), hi = upk(acc[r][1]);
        av[r][0] = lo.x; av[r][1] = lo.y; av[r][2] = hi.x; av[r][3] = hi.y;
    }
    {
        const int T = blockIdx.x >> 1;
        const uint32_t jp = (uint32_t)((blockIdx.x & 1) * 16 + 2 * ty);
#pragma unroll
        for (int c = 0; c < 4; c++) {
            int f = 4 * tx + c;
            uint32_t bidx = (uint32_t)T * 2048u + (uint32_t)f * 32u + jp;
            g_hT[bidx]     = f16x2_of(av[0][c], av[1][c]);
            g_hT[bidx + 1] = f16x2_of(av[2][c], av[3][c]);
        }
    }
    float mloc = -3.4e38f;
#pragma unroll
    for (int r = 0; r < 4; r++) {
        float s1 = av[r][0]*as1[4*tx] + av[r][1]*as1[4*tx+1] + av[r][2]*as1[4*tx+2] + av[r][3]*as1[4*tx+3];
        float s2 = av[r][0]*as2[4*tx] + av[r][1]*as2[4*tx+1] + av[r][2]*as2[4*tx+2] + av[r][3]*as2[4*tx+3];
#pragma unroll
        for (int off = 8; off >= 1; off >>= 1) {
            s1 += __shfl_xor_sync(0xffffffffu, s1, off);
            s2 += __shfl_xor_sync(0xffffffffu, s2, off);
        }
        if (tx == 0) { g_hl[i0 + 4 * ty + r] = s1; g_hr[i0 + 4 * ty + r] = s2; }
        mloc = fmaxf(mloc, s2);
    }
    red[t] = mloc;
    __syncthreads();
    for (int s = 64; s > 0; s >>= 1) { if (t < s) red[t] = fmaxf(red[t], red[t + s]); __syncthreads(); }
    if (t == 0) atomicMax(&g_hrmaxkey, fkey(red[0]));
    if (blockIdx.x == 0 && t == 0) { g_scalars[1] = fabsf(Wei[0]); g_scalars[2] = fabsf(Wsi[0]); }
}

// ============ D: fused attention (bitmask, 1-deep ad prefetch, 6-stage Ht ring) ============
__global__ void __launch_bounds__(256, 2) k_attn(const float* __restrict__ adj_ad) {
    extern __shared__ float4 smem4[];
    char* base = (char*)smem4;
    const uint32_t sb = smem_u32(base);

    const int t = threadIdx.x, wid = t >> 5, l = t & 31;
    const int i0 = blockIdx.x * BI, split = blockIdx.y, j0b = split * JCHUNK;
    const int T0 = split * NT;

    if (t < 128) *(float4*)(base + SM_HR + 16 * t) = *(const float4*)&g_hr[j0b + 4 * t];

    const float hrmax = fkeyinv(g_hrmaxkey);
    const float wei = g_scalars[1], wsi = g_scalars[2];
    const int r1 = t >> 2, q1 = t & 3;
    const float hl_r = g_hl[i0 + r1];
    float smax = hl_r + hrmax;
    const float m_r = fmaf(wei, fmaxf(smax, 0.2f * smax), wsi);

    const int iw = wid & 3, fh = wid >> 2;
    const uint32_t aRow = (uint32_t)((l & 7) | (l & 8));
    const uint32_t aOff = (uint32_t)(16 * iw + aRow) * 144u + (uint32_t)(((l >> 4) & 1) * 16);
    const uint32_t bRow = (uint32_t)(32 * fh + ((l & 7) | (((l >> 4) & 1) << 3)));
    const uint32_t bOff = bRow * 144u + (uint32_t)(((l >> 3) & 1) * 16);

    float acc[16];
#pragma unroll
    for (int i = 0; i < 16; i++) acc[i] = 0.f;
    float zl = 0.f;

    // Ht ring prologue
#pragma unroll
    for (int s = 0; s < 5; s++) {
        const char* src = (const char*)&g_hT[(uint32_t)(T0 + s) * 2048u];
#pragma unroll
        for (int k = 0; k < 2; k++) {
            int c = k * 256 + t, f = c >> 3, ch = c & 7;
            cpa16(sb + SM_HT + s * HTSTG + f * 144 + ch * 16, src + f * 128 + ch * 16);
        }
        CP_COMMIT();
    }
    // ad tile 0 + mask word 0 in regs (1-deep, R13-style)
    const uint32_t* maskrow = &g_mask[(size_t)(i0 + r1) * (NN / 32) + split * 16];
    float4 adreg[4];
    {
        const float4* ap = (const float4*)&adj_ad[(size_t)(i0 + r1) * NN + j0b + q1 * 16];
#pragma unroll
        for (int k = 0; k < 4; k++) adreg[k] = ap[k];
    }
    uint32_t mw = maskrow[q1 >> 1];
    const int msh = (q1 & 1) * 16;
    __syncthreads();   // hr visible

    for (int jt = 0; jt < NT; jt++) {
        const int cur = jt & 1;
        // ---- phase 1 (registers): p -> fp16 into P[cur] ----
        {
            const float* hrs = (const float*)(base + SM_HR) + jt * 64 + q1 * 16;
            const uint32_t bits = mw >> msh;
            uint32_t pw[8];
#pragma unroll
            for (int k = 0; k < 4; k++) {
                float4 ad4 = adreg[k];
                float4 hr4 = *(const float4*)(hrs + 4 * k);
                float pv[4];
                {
                    float s = hl_r + hr4.x, lr = fmaxf(s, 0.2f * s);
                    pv[0] = (bits & (1u << (4 * k + 0))) ? __expf(fmaf(wei, lr, fmaf(wsi, ad4.x, -m_r))) : 0.f;
                }
                {
                    float s = hl_r + hr4.y, lr = fmaxf(s, 0.2f * s);
                    pv[1] = (bits & (1u << (4 * k + 1))) ? __expf(fmaf(wei, lr, fmaf(wsi, ad4.y, -m_r))) : 0.f;
                }
                {
                    float s = hl_r + hr4.z, lr = fmaxf(s, 0.2f * s);
                    pv[2] = (bits & (1u << (4 * k + 2))) ? __expf(fmaf(wei, lr, fmaf(wsi, ad4.z, -m_r))) : 0.f;
                }
                {
                    float s = hl_r + hr4.w, lr = fmaxf(s, 0.2f * s);
                    pv[3] = (bits & (1u << (4 * k + 3))) ? __expf(fmaf(wei, lr, fmaf(wsi, ad4.w, -m_r))) : 0.f;
                }
                zl += (pv[0] + pv[1]) + (pv[2] + pv[3]);
                pw[2*k]   = f16x2_of(pv[0], pv[1]);
                pw[2*k+1] = f16x2_of(pv[2], pv[3]);
            }
            char* pb = base + SM_P + cur * HTSTG + r1 * 144 + q1 * 32;
            *(uint4*)pb        = make_uint4(pw[0], pw[1], pw[2], pw[3]);
            *(uint4*)(pb + 16) = make_uint4(pw[4], pw[5], pw[6], pw[7]);
        }

        // prefetch ad + mask for tile jt+1 (1-deep)
        if (jt + 1 < NT) {
            const float4* ap = (const float4*)&adj_ad[(size_t)(i0 + r1) * NN + j0b + (jt + 1) * BJ + q1 * 16];
#pragma unroll
            for (int k = 0; k < 4; k++) adreg[k] = ap[k];
            mw = maskrow[(jt + 1) * 2 + (q1 >> 1)];
        }

        CP_WAIT4();
        __syncthreads();

        // issue Ht(jt+5)
        {
            const int jsrc = (jt + 5 < NT) ? jt + 5 : NT - 1;
            const char* src = (const char*)&g_hT[(uint32_t)(T0 + jsrc) * 2048u];
            const int st = (jt + 5) % 6;
#pragma unroll
            for (int k = 0; k < 2; k++) {
                int c = k * 256 + t, f = c >> 3, ch = c & 7;
                cpa16(sb + SM_HT + st * HTSTG + f * 144 + ch * 16, src + f * 128 + ch * 16);
            }
            CP_COMMIT();
        }

        // ---- phase 2: 16 mma ----
        const uint32_t pA = sb + SM_P + (uint32_t)(cur * HTSTG) + aOff;
        const uint32_t hB = sb + SM_HT + (uint32_t)((jt % 6) * HTSTG) + bOff;
#pragma unroll
        for (int ks = 0; ks < 4; ks++) {
            const uint32_t ka = (uint32_t)ks * 32u;
            uint32_t ap4[4], bh0[4], bh1[4];
            ldm4(ap4, pA + ka);
            ldm4(bh0, hB + ka);
            ldm4(bh1, hB + 16u * 144u + ka);
            mma16816(acc + 0,  ap4, bh0[0], bh0[1]);
            mma16816(acc + 4,  ap4, bh0[2], bh0[3]);
            mma16816(acc + 8,  ap4, bh1[0], bh1[1]);
            mma16816(acc + 12, ap4, bh1[2], bh1[3]);
        }
    }
    CP_WAITALL();

    zl += __shfl_xor_sync(0xffffffffu, zl, 1);
    zl += __shfl_xor_sync(0xffffffffu, zl, 2);
    if (q1 == 0) g_Z[split * NN + i0 + r1] = zl;

    {
        const int g = l >> 2, tig = l & 3;
#pragma unroll
        for (int nt = 0; nt < 4; nt++) {
            const int col = 32 * fh + 8 * nt + 2 * tig;
            const size_t b0 = ((size_t)split * NN + i0 + 16 * iw + g) * FF + col;
            const size_t b1 = b0 + (size_t)8 * FF;
            *(float2*)&g_acc[b0] = make_float2(acc[4 * nt + 0], acc[4 * nt + 1]);
            *(float2*)&g_acc[b1] = make_float2(acc[4 * nt + 2], acc[4 * nt + 3]);
        }
    }
}

// ============ E: combine (float4), normalize, ELU ============
__global__ void __launch_bounds__(256) k_combine(float* __restrict__ out) {
    const int v = blockIdx.x * 256 + threadIdx.x;
    const int i = v >> 4;
    float4 num = make_float4(0.f, 0.f, 0.f, 0.f);
    float den = 0.f;
#pragma unroll
    for (int s = 0; s < SPLITJ; s++) {
        float4 x = *(const float4*)&g_acc[(size_t)s * NN * FF + (size_t)v * 4];
        num.x += x.x; num.y += x.y; num.z += x.z; num.w += x.w;
        den += g_Z[s * NN + i];
    }
    float inv = 1.0f / den;
    float4 r = make_float4(num.x * inv, num.y * inv, num.z * inv, num.w * inv);
    r.x = (r.x > 0.f) ? r.x : expm1f(r.x);
    r.y = (r.y > 0.f) ? r.y : expm1f(r.y);
    r.z = (r.z > 0.f) ? r.z : expm1f(r.z);
    r.w = (r.w > 0.f) ? r.w : expm1f(r.w);
    *(float4*)&out[(size_t)v * 4] = r;
}

extern "C" void kernel_launch(void* const* d_in, const int* in_sizes, int n_in,
                              void* d_out, int out_size) {
    (void)in_sizes; (void)n_in; (void)out_size;
    const float* input  = (const float*)d_in[0];
    const float* W      = (const float*)d_in[1];
    const float* a      = (const float*)d_in[2];
    const float* W_si   = (const float*)d_in[3];
    const float* W_ei   = (const float*)d_in[4];
    const float* adj_ad = (const float*)d_in[5];
    const int*   adj    = (const int*)d_in[6];
    float* out = (float*)d_out;

    cudaFuncSetAttribute(k_attn, cudaFuncAttributeMaxDynamicSharedMemorySize, SM_BYTES);

    k_mask<<<NN * (NN / 32) / 256, 256>>>(adj);
    k_gemm_h<<<NN / 32, 128>>>(input, W, a, W_si, W_ei);
    k_attn<<<dim3(NN / BI, SPLITJ), 256, SM_BYTES>>>(adj_ad);
    k_combine<<<NN * FF / 1024, 256>>>(out);
}

// round 17
// speedup vs baseline: 1.4303x; 1.2768x over previous
#include <cuda_runtime.h>
#include <cuda_fp16.h>
#include <math.h>
#include <stdint.h>

#define NN 8192
#define KK 512
#define FF 64
#define SPLITJ 16
#define JCHUNK (NN / SPLITJ)   // 512
#define BI 64
#define BJ 64
#define NT (JCHUNK / BJ)       // 8

// k_attn smem layout (bytes)
#define HTSTG 9216
#define SM_HT 0                      // 6 stages = 55296
#define SM_P  (6 * HTSTG)            // 2 x 9216
#define SM_HR (SM_P + 2 * HTSTG)     // 2048
#define SM_BYTES (SM_HR + 2048)      // 75776

__device__ float g_hl[NN];
__device__ float g_hr[NN];
__device__ float g_scalars[4];                    // [1]=|W_ei| [2]=|W_si|
__device__ unsigned g_hrmaxkey;                   // order-preserving float key
__device__ uint32_t g_hT[128u * 2048u];           // [tile][f][jpair] f16x2, 1 MB
__device__ float g_acc[(size_t)SPLITJ * NN * FF]; // 32 MB
__device__ float g_Z[SPLITJ * NN];

// ---------- helpers ----------
__device__ __forceinline__ unsigned long long pk2(float x, float y) {
    unsigned long long r; asm("mov.b64 %0, {%1,%2};" : "=l"(r) : "f"(x), "f"(y)); return r;
}
__device__ __forceinline__ void fma2(unsigned long long& d, unsigned long long a, unsigned long long b) {
    asm("fma.rn.f32x2 %0, %1, %2, %0;" : "+l"(d) : "l"(a), "l"(b));
}
__device__ __forceinline__ float2 upk(unsigned long long v) {
    float2 f; asm("mov.b64 {%0,%1}, %2;" : "=f"(f.x), "=f"(f.y) : "l"(v)); return f;
}
__device__ __forceinline__ uint32_t smem_u32(const void* p) {
    uint32_t a; asm("{ .reg .u64 t; cvta.to.shared.u64 t, %1; cvt.u32.u64 %0, t; }" : "=r"(a) : "l"(p)); return a;
}
__device__ __forceinline__ void cpa16(uint32_t dst, const void* src) {
    asm volatile("cp.async.cg.shared.global [%0], [%1], 16;" :: "r"(dst), "l"(src));
}
#define CP_COMMIT()  asm volatile("cp.async.commit_group;" ::: "memory")
#define CP_WAIT1()   asm volatile("cp.async.wait_group 1;" ::: "memory")
#define CP_WAIT4()   asm volatile("cp.async.wait_group 4;" ::: "memory")
#define CP_WAITALL() asm volatile("cp.async.wait_all;" ::: "memory")

__device__ __forceinline__ uint32_t f16x2_of(float lo, float hi) {
    uint32_t r; asm("cvt.rn.f16x2.f32 %0, %1, %2;" : "=r"(r) : "f"(hi), "f"(lo)); return r;
}
__device__ __forceinline__ void ldm4(uint32_t* r, uint32_t addr) {
    asm volatile("ldmatrix.sync.aligned.m8n8.x4.shared.b16 {%0,%1,%2,%3}, [%4];"
                 : "=r"(r[0]), "=r"(r[1]), "=r"(r[2]), "=r"(r[3]) : "r"(addr));
}
__device__ __forceinline__ void mma16816(float* d, const uint32_t* a, uint32_t b0, uint32_t b1) {
    asm("mma.sync.aligned.m16n8k16.row.col.f32.f16.f16.f32 "
        "{%0,%1,%2,%3}, {%4,%5,%6,%7}, {%8,%9}, {%0,%1,%2,%3};"
        : "+f"(d[0]), "+f"(d[1]), "+f"(d[2]), "+f"(d[3])
        : "r"(a[0]), "r"(a[1]), "r"(a[2]), "r"(a[3]), "r"(b0), "r"(b1));
}
__device__ __forceinline__ unsigned fkey(float f) {
    unsigned u = __float_as_uint(f);
    return (u & 0x80000000u) ? ~u : (u | 0x80000000u);
}
__device__ __forceinline__ float fkeyinv(unsigned k) {
    unsigned u = (k & 0x80000000u) ? (k ^ 0x80000000u) : ~k;
    return __uint_as_float(u);
}

// ============ A: pipelined gemm + fused hl/hr/hrmax + fp16 hT image ============
__global__ void __launch_bounds__(128) k_gemm_h(const float* __restrict__ X,
                                                const float* __restrict__ W,
                                                const float* __restrict__ a,
                                                const float* __restrict__ Wsi,
                                                const float* __restrict__ Wei) {
    __shared__ float xs[32][36];
    __shared__ float ws[3][32][68];
    __shared__ float as1[FF], as2[FF], red[128];
    const int t = threadIdx.x, tx = t & 15, ty = t >> 4;
    const int i0 = blockIdx.x * 32;
    if (t < FF) as1[t] = a[t]; else as2[t - FF] = a[t];

    const uint32_t ws_sb = smem_u32(&ws[0][0][0]);
    auto issueW = [&](int s, int c0) {
#pragma unroll
        for (int k = 0; k < 4; k++) {
            int c = k * 128 + t, row = c >> 4, col4 = (c & 15) * 4;
            cpa16(ws_sb + (uint32_t)((s * 2176 + row * 68 + col4) * 4),
                  W + (size_t)(c0 + row) * FF + col4);
        }
    };
    const int xrow = t >> 2, xk0 = (t & 3) * 8;
    float4 xr0, xr1;
    auto loadX = [&](int c0) {
        const float* p = &X[(size_t)(i0 + xrow) * KK + c0 + xk0];
        xr0 = *(const float4*)p; xr1 = *(const float4*)(p + 4);
    };

    issueW(0, 0);  CP_COMMIT();
    issueW(1, 32); CP_COMMIT();
    loadX(0);

    unsigned long long acc[4][2];
#pragma unroll
    for (int r = 0; r < 4; r++) { acc[r][0] = 0ULL; acc[r][1] = 0ULL; }

    for (int ct = 0; ct < 16; ct++) {
        CP_WAIT1();
        __syncthreads();
        xs[xk0 + 0][xrow] = xr0.x; xs[xk0 + 1][xrow] = xr0.y;
        xs[xk0 + 2][xrow] = xr0.z; xs[xk0 + 3][xrow] = xr0.w;
        xs[xk0 + 4][xrow] = xr1.x; xs[xk0 + 5][xrow] = xr1.y;
        xs[xk0 + 6][xrow] = xr1.z; xs[xk0 + 7][xrow] = xr1.w;
        if (ct + 1 < 16) loadX(32 * (ct + 1));
        { int cs = (ct + 2 < 16) ? ct + 2 : 15; issueW((ct + 2) % 3, 32 * cs); }
        CP_COMMIT();
        __syncthreads();
        const int st = ct % 3;
#pragma unroll
        for (int kk = 0; kk < 32; kk++) {
            float4 w4 = *(const float4*)&ws[st][kk][4 * tx];
            unsigned long long w01 = pk2(w4.x, w4.y), w23 = pk2(w4.z, w4.w);
            float4 a4 = *(const float4*)&xs[kk][4 * ty];
            float av[4] = {a4.x, a4.y, a4.z, a4.w};
#pragma unroll
            for (int r = 0; r < 4; r++) {
                unsigned long long ar = pk2(av[r], av[r]);
                fma2(acc[r][0], ar, w01); fma2(acc[r][1], ar, w23);
            }
        }
    }
    CP_WAITALL();

    float av[4][4];
#pragma unroll
    for (int r = 0; r < 4; r++) {
        float2 lo = upk(acc[r][0]), hi = upk(acc[r][1]);
        av[r][0] = lo.x; av[r][1] = lo.y; av[r][2] = hi.x; av[r][3] = hi.y;
    }
    {
        const int T = blockIdx.x >> 1;
        const uint32_t jp = (uint32_t)((blockIdx.x & 1) * 16 + 2 * ty);
#pragma unroll
        for (int c = 0; c < 4; c++) {
            int f = 4 * tx + c;
            uint32_t bidx = (uint32_t)T * 2048u + (uint32_t)f * 32u + jp;
            g_hT[bidx]     = f16x2_of(av[0][c], av[1][c]);
            g_hT[bidx + 1] = f16x2_of(av[2][c], av[3][c]);
        }
    }
    float mloc = -3.4e38f;
#pragma unroll
    for (int r = 0; r < 4; r++) {
        float s1 = av[r][0]*as1[4*tx] + av[r][1]*as1[4*tx+1] + av[r][2]*as1[4*tx+2] + av[r][3]*as1[4*tx+3];
        float s2 = av[r][0]*as2[4*tx] + av[r][1]*as2[4*tx+1] + av[r][2]*as2[4*tx+2] + av[r][3]*as2[4*tx+3];
#pragma unroll
        for (int off = 8; off >= 1; off >>= 1) {
            s1 += __shfl_xor_sync(0xffffffffu, s1, off);
            s2 += __shfl_xor_sync(0xffffffffu, s2, off);
        }
        if (tx == 0) { g_hl[i0 + 4 * ty + r] = s1; g_hr[i0 + 4 * ty + r] = s2; }
        mloc = fmaxf(mloc, s2);
    }
    red[t] = mloc;
    __syncthreads();
    for (int s = 64; s > 0; s >>= 1) { if (t < s) red[t] = fmaxf(red[t], red[t + s]); __syncthreads(); }
    if (t == 0) atomicMax(&g_hrmaxkey, fkey(red[0]));
    if (blockIdx.x == 0 && t == 0) { g_scalars[1] = fabsf(Wei[0]); g_scalars[2] = fabsf(Wsi[0]); }
}

// ============ D: fused attention — phase1/phase2 software-pipelined ============
__global__ void __launch_bounds__(256, 2) k_attn(const float* __restrict__ adj_ad,
                                                 const int* __restrict__ adj) {
    extern __shared__ float4 smem4[];
    char* base = (char*)smem4;
    const uint32_t sb = smem_u32(base);

    const int t = threadIdx.x, wid = t >> 5, l = t & 31;
    const int i0 = blockIdx.x * BI, split = blockIdx.y, j0b = split * JCHUNK;
    const int T0 = split * NT;

    if (t < 128) *(float4*)(base + SM_HR + 16 * t) = *(const float4*)&g_hr[j0b + 4 * t];

    const float hrmax = fkeyinv(g_hrmaxkey);
    const float wei = g_scalars[1], wsi = g_scalars[2];
    const int r1 = t >> 2, q1 = t & 3;
    const float hl_r = g_hl[i0 + r1];
    float smax = hl_r + hrmax;
    const float m_r = fmaf(wei, fmaxf(smax, 0.2f * smax), wsi);

    const int iw = wid & 3, fh = wid >> 2;
    const uint32_t aRow = (uint32_t)((l & 7) | (l & 8));
    const uint32_t aOff = (uint32_t)(16 * iw + aRow) * 144u + (uint32_t)(((l >> 4) & 1) * 16);
    const uint32_t bRow = (uint32_t)(32 * fh + ((l & 7) | (((l >> 4) & 1) << 3)));
    const uint32_t bOff = bRow * 144u + (uint32_t)(((l >> 3) & 1) * 16);

    float acc[16];
#pragma unroll
    for (int i = 0; i < 16; i++) acc[i] = 0.f;
    float zl = 0.f;

    float4 adreg[4];
    int4   ajreg[4];
    auto loadAdj = [&](int tile) {
        const float4* ap = (const float4*)&adj_ad[(size_t)(i0 + r1) * NN + j0b + tile * BJ + q1 * 16];
        const int4*   jp = (const int4*)&adj[(size_t)(i0 + r1) * NN + j0b + tile * BJ + q1 * 16];
#pragma unroll
        for (int k = 0; k < 4; k++) { adreg[k] = ap[k]; ajreg[k] = jp[k]; }
    };
    auto issueHt = [&](int tile) {
        const int jsrc = (tile < NT) ? tile : NT - 1;
        const char* src = (const char*)&g_hT[(uint32_t)(T0 + jsrc) * 2048u];
        const int st = tile % 6;
#pragma unroll
        for (int k = 0; k < 2; k++) {
            int c = k * 256 + t, f = c >> 3, ch = c & 7;
            cpa16(sb + SM_HT + st * HTSTG + f * 144 + ch * 16, src + f * 128 + ch * 16);
        }
        CP_COMMIT();
    };
    // phase1 for tile `tile` using current adreg/ajreg -> P[tile&1]
    auto phase1 = [&](int tile) {
        const float* hrs = (const float*)(base + SM_HR) + tile * 64 + q1 * 16;
        uint32_t pw[8];
#pragma unroll
        for (int k = 0; k < 4; k++) {
            float4 ad4 = adreg[k];
            int4   aj4 = ajreg[k];
            float4 hr4 = *(const float4*)(hrs + 4 * k);
            float pv[4];
            {
                float s = hl_r + hr4.x, lr = fmaxf(s, 0.2f * s);
                pv[0] = (aj4.x > 0) ? __expf(fmaf(wei, lr, fmaf(wsi, ad4.x, -m_r))) : 0.f;
            }
            {
                float s = hl_r + hr4.y, lr = fmaxf(s, 0.2f * s);
                pv[1] = (aj4.y > 0) ? __expf(fmaf(wei, lr, fmaf(wsi, ad4.y, -m_r))) : 0.f;
            }
            {
                float s = hl_r + hr4.z, lr = fmaxf(s, 0.2f * s);
                pv[2] = (aj4.z > 0) ? __expf(fmaf(wei, lr, fmaf(wsi, ad4.z, -m_r))) : 0.f;
            }
            {
                float s = hl_r + hr4.w, lr = fmaxf(s, 0.2f * s);
                pv[3] = (aj4.w > 0) ? __expf(fmaf(wei, lr, fmaf(wsi, ad4.w, -m_r))) : 0.f;
            }
            zl += (pv[0] + pv[1]) + (pv[2] + pv[3]);
            pw[2*k]   = f16x2_of(pv[0], pv[1]);
            pw[2*k+1] = f16x2_of(pv[2], pv[3]);
        }
        char* pb = base + SM_P + (tile & 1) * HTSTG + r1 * 144 + q1 * 32;
        *(uint4*)pb        = make_uint4(pw[0], pw[1], pw[2], pw[3]);
        *(uint4*)(pb + 16) = make_uint4(pw[4], pw[5], pw[6], pw[7]);
    };

    // ---- prologue: Ht 0..4 in flight; phase1(0) -> P[0] ----
#pragma unroll
    for (int s = 0; s < 5; s++) issueHt(s);
    loadAdj(0);
    __syncthreads();          // hr visible (phase1 reads hr smem)
    phase1(0);
    loadAdj(1);
    CP_WAIT4();               // Ht[0] landed (≤4 outstanding of g0..g4)
    __syncthreads();          // P[0] visible cross-warp

    for (int jt = 0; jt < NT; jt++) {
        issueHt(jt + 5);      // stage (jt+5)%6; conflicts only with phase2(jt-1), barriered

        // phase1(jt+1) -> P[(jt+1)&1]  (overlaps phase2(jt) in this barrier interval)
        if (jt + 1 < NT) {
            phase1(jt + 1);
            if (jt + 2 < NT) loadAdj(jt + 2);
        }

        // ---- phase2(jt): P[jt&1] x Ht[jt%6] ----
        const uint32_t pA = sb + SM_P + (uint32_t)((jt & 1) * HTSTG) + aOff;
        const uint32_t hB = sb + SM_HT + (uint32_t)((jt % 6) * HTSTG) + bOff;
#pragma unroll
        for (int ks = 0; ks < 4; ks++) {
            const uint32_t ka = (uint32_t)ks * 32u;
            uint32_t ap4[4], bh0[4], bh1[4];
            ldm4(ap4, pA + ka);
            ldm4(bh0, hB + ka);
            ldm4(bh1, hB + 16u * 144u + ka);
            mma16816(acc + 0,  ap4, bh0[0], bh0[1]);
            mma16816(acc + 4,  ap4, bh0[2], bh0[3]);
            mma16816(acc + 8,  ap4, bh1[0], bh1[1]);
            mma16816(acc + 12, ap4, bh1[2], bh1[3]);
        }

        CP_WAIT4();           // Ht[jt+1] landed
        __syncthreads();      // P[(jt+1)&1] visible; phase2(jt) complete for all warps
    }
    CP_WAITALL();

    // z writeout
    zl += __shfl_xor_sync(0xffffffffu, zl, 1);
    zl += __shfl_xor_sync(0xffffffffu, zl, 2);
    if (q1 == 0) g_Z[split * NN + i0 + r1] = zl;

    // acc writeout
    {
        const int g = l >> 2, tig = l & 3;
#pragma unroll
        for (int nt = 0; nt < 4; nt++) {
            const int col = 32 * fh + 8 * nt + 2 * tig;
            const size_t b0 = ((size_t)split * NN + i0 + 16 * iw + g) * FF + col;
            const size_t b1 = b0 + (size_t)8 * FF;
            *(float2*)&g_acc[b0] = make_float2(acc[4 * nt + 0], acc[4 * nt + 1]);
            *(float2*)&g_acc[b1] = make_float2(acc[4 * nt + 2], acc[4 * nt + 3]);
        }
    }
}

// ============ E: combine (float4), normalize, ELU ============
__global__ void __launch_bounds__(256) k_combine(float* __restrict__ out) {
    const int v = blockIdx.x * 256 + threadIdx.x;
    const int i = v >> 4;
    float4 num = make_float4(0.f, 0.f, 0.f, 0.f);
    float den = 0.f;
#pragma unroll
    for (int s = 0; s < SPLITJ; s++) {
        float4 x = *(const float4*)&g_acc[(size_t)s * NN * FF + (size_t)v * 4];
        num.x += x.x; num.y += x.y; num.z += x.z; num.w += x.w;
        den += g_Z[s * NN + i];
    }
    float inv = 1.0f / den;
    float4 r = make_float4(num.x * inv, num.y * inv, num.z * inv, num.w * inv);
    r.x = (r.x > 0.f) ? r.x : expm1f(r.x);
    r.y = (r.y > 0.f) ? r.y : expm1f(r.y);
    r.z = (r.z > 0.f) ? r.z : expm1f(r.z);
    r.w = (r.w > 0.f) ? r.w : expm1f(r.w);
    *(float4*)&out[(size_t)v * 4] = r;
}

extern "C" void kernel_launch(void* const* d_in, const int* in_sizes, int n_in,
                              void* d_out, int out_size) {
    (void)in_sizes; (void)n_in; (void)out_size;
    const float* input  = (const float*)d_in[0];
    const float* W      = (const float*)d_in[1];
    const float* a      = (const float*)d_in[2];
    const float* W_si   = (const float*)d_in[3];
    const float* W_ei   = (const float*)d_in[4];
    const float* adj_ad = (const float*)d_in[5];
    const int*   adj    = (const int*)d_in[6];
    float* out = (float*)d_out;

    cudaFuncSetAttribute(k_attn, cudaFuncAttributeMaxDynamicSharedMemorySize, SM_BYTES);

    k_gemm_h<<<NN / 32, 128>>>(input, W, a, W_si, W_ei);
    k_attn<<<dim3(NN / BI, SPLITJ), 256, SM_BYTES>>>(adj_ad, adj);
    k_combine<<<NN * FF / 1024, 256>>>(out);
}